// round 14
// baseline (speedup 1.0000x reference)
#include <cuda_runtime.h>
#include <cuda_bf16.h>
#include <cuda_fp16.h>
#include <math.h>
#include <stdint.h>
#include <stddef.h>

#define SS 512
#define DD 1024
#define NNH 4096
#define VV 32000
#define MROWS 1024
#define MMDD (MROWS * DD)
#define EPSLN 1e-5f
#define GRU_CTAS 128

// ---------------- device scratch ----------------
__device__ float  g_x[MROWS * DD];
__device__ float  g_gi[MROWS * 3 * DD];
__device__ float  g_psum[2 * MROWS * DD];
__device__ float  g_h[2][2 * DD];
__device__ double g_part[10 * 512];
__device__ float  g_scale[10];
__device__ float  g_scaleinv[10];
__device__ volatile unsigned g_flags[GRU_CTAS * 32];
__device__ unsigned g_ack;

// fp16 buffers
__device__ __half g_w16ih[3 * DD * DD];
__device__ __half g_q16syn[4 * NNH * DD];
__device__ __half g_q16out[4 * NNH * DD];
__device__ __half g_q16head[VV * DD];
__device__ __half g_x16[MROWS * DD];
__device__ __half g_h16[MROWS * NNH];
__device__ __half g_y16[MROWS * DD];

// ---------------- asm helpers ----------------
#define CP16(dst, src) asm volatile("cp.async.cg.shared.global [%0], [%1], 16;" :: "r"(dst), "l"(src))
#define CPCOMMIT() asm volatile("cp.async.commit_group;")
#define CPWAIT_0() asm volatile("cp.async.wait_group 0;")
#define LDSM4(r, addr) asm volatile( \
    "ldmatrix.sync.aligned.m8n8.x4.shared.b16 {%0,%1,%2,%3}, [%4];" \
    : "=r"((r)[0]), "=r"((r)[1]), "=r"((r)[2]), "=r"((r)[3]) : "r"(addr))
#define HMMA16816(d, a, b0, b1) asm volatile( \
    "mma.sync.aligned.m16n8k16.row.col.f32.f16.f16.f32 " \
    "{%0,%1,%2,%3},{%4,%5,%6,%7},{%8,%9},{%0,%1,%2,%3};" \
    : "+f"((d)[0]), "+f"((d)[1]), "+f"((d)[2]), "+f"((d)[3]) \
    : "r"((a)[0]), "r"((a)[1]), "r"((a)[2]), "r"((a)[3]), "r"(b0), "r"(b1))

__device__ __forceinline__ unsigned short f16bits(float x) {
    return __half_as_ushort(__float2half(x));
}
__device__ __forceinline__ unsigned long long pk2(float x, float y) {
    unsigned long long r;
    asm("mov.b64 %0, {%1, %2};" : "=l"(r) : "f"(x), "f"(y));
    return r;
}
__device__ __forceinline__ void ffma2(unsigned long long& d, unsigned long long a, unsigned long long b) {
    asm("fma.rn.f32x2 %0, %1, %2, %0;" : "+l"(d) : "l"(a), "l"(b));
}
__device__ __forceinline__ float2 unpk(unsigned long long v) {
    float2 f;
    asm("mov.b64 {%0, %1}, %2;" : "=f"(f.x), "=f"(f.y) : "l"(v));
    return f;
}

// ---------------- abs-mean scale ----------------
__global__ __launch_bounds__(256, 2) void absmean_part(const float4* __restrict__ src, long n4, int slot) {
    __shared__ double sred[256];
    double a[8];
#pragma unroll
    for (int c = 0; c < 8; c++) a[c] = 0.0;
    const long stride = (long)gridDim.x * 256;
    long i = (long)blockIdx.x * 256 + threadIdx.x;
    for (; i + 7 * stride < n4; i += 8 * stride) {
        float4 v[8];
#pragma unroll
        for (int c = 0; c < 8; c++) v[c] = src[i + c * stride];
#pragma unroll
        for (int c = 0; c < 8; c++)
            a[c] += (double)(fabsf(v[c].x) + fabsf(v[c].y)) + (double)(fabsf(v[c].z) + fabsf(v[c].w));
    }
    for (; i < n4; i += stride) {
        float4 v = src[i];
        a[0] += (double)(fabsf(v.x) + fabsf(v.y)) + (double)(fabsf(v.z) + fabsf(v.w));
    }
    sred[threadIdx.x] = ((a[0] + a[1]) + (a[2] + a[3])) + ((a[4] + a[5]) + (a[6] + a[7]));
    __syncthreads();
#pragma unroll
    for (int o = 128; o > 0; o >>= 1) {
        if ((int)threadIdx.x < o) sred[threadIdx.x] += sred[threadIdx.x + o];
        __syncthreads();
    }
    if (threadIdx.x == 0) g_part[slot * 512 + blockIdx.x] = sred[0];
}

__global__ void absmean_final(int base) {
    __shared__ double sred[256];
    int slot = base + blockIdx.x, t = threadIdx.x;
    sred[t] = g_part[slot * 512 + t] + g_part[slot * 512 + 256 + t];
    __syncthreads();
#pragma unroll
    for (int o = 128; o > 0; o >>= 1) {
        if (t < o) sred[t] += sred[t + o];
        __syncthreads();
    }
    if (t == 0) {
        double cnt = (slot < 2) ? (double)VV * DD : (double)NNH * DD;
        double s = sred[0] / cnt + 1e-8;
        g_scale[slot]    = (float)s;
        g_scaleinv[slot] = (float)(1.0 / s);
    }
}

// ---------------- weight conversion ----------------
__global__ void tern_quant16(const float4* __restrict__ w, ushort4* __restrict__ q,
                             int slot, int n4) {
    int i = blockIdx.x * 256 + threadIdx.x;
    if (i >= n4) return;
    float inv = g_scaleinv[slot];
    float4 v = w[i];
    ushort4 o;
    o.x = f16bits(rintf(fminf(fmaxf(v.x * inv, -1.f), 1.f)));
    o.y = f16bits(rintf(fminf(fmaxf(v.y * inv, -1.f), 1.f)));
    o.z = f16bits(rintf(fminf(fmaxf(v.z * inv, -1.f), 1.f)));
    o.w = f16bits(rintf(fminf(fmaxf(v.w * inv, -1.f), 1.f)));
    q[i] = o;
}

// ---------------- embedding (fp16 out) + fused wih fp16 conversion ----------------
__global__ void embed_kernel(const int* __restrict__ ids, const float* __restrict__ emb,
                             const float* __restrict__ pos, __half* __restrict__ e16,
                             const float* __restrict__ wih, __half* __restrict__ w16) {
    int i = blockIdx.x * 256 + threadIdx.x;
    int d = i & (DD - 1);
    int s = (i >> 10) & (SS - 1);
    int b = i >> 19;
    int tok = ids[b * SS + s];
    float w = emb[(size_t)tok * DD + d];
    float tn = g_scale[0] * rintf(fminf(fmaxf(w * g_scaleinv[0], -1.f), 1.f));
    e16[i] = __float2half(tn + pos[s * DD + d]);
    w16[i]            = __float2half(wih[i]);
    w16[i + MMDD]     = __float2half(wih[i + MMDD]);
    w16[i + 2 * MMDD] = __float2half(wih[i + 2 * MMDD]);
}

// ---------------- single-pass FP16 GEMM NT, K-stage 64, 2-buffer ----------------
// smem: per stage 256 rows x 144B (A rows 0..127, B rows at +18432)
#define HG_STAGE 36864
#define HG_SMEM (2 * HG_STAGE)   // 73728 B

template<bool RELU, bool OUT_F16, bool SCALED>
__global__ __launch_bounds__(256) void hgemm(
    const __half* __restrict__ A, const __half* __restrict__ B,
    float* __restrict__ C, __half* __restrict__ C16,
    const float* __restrict__ bias,
    int M, int N, int Kld, int kLen, int slot)
{
    extern __shared__ __align__(16) __half smh[];
    const int t = threadIdx.x;
    const int lane = t & 31;
    const int w = t >> 5;
    const int warpM = (w >> 1) << 5;
    const int warpN = (w & 1) << 6;
    const int bm = blockIdx.y << 7, bn = blockIdx.x << 7;
    const int kOff = blockIdx.z * kLen;
    if (gridDim.z > 1) C += (size_t)blockIdx.z * ((size_t)M * N);

    const __half* gA = A + (size_t)bm * Kld + kOff;
    const __half* gB = B + (size_t)bn * Kld + kOff;
    const unsigned uS = (unsigned)__cvta_generic_to_shared(smh);

    // loader mapping: row = t>>1 (0..127), 4 x 16B chunks starting at (t&1)*4
    const int lrow = t >> 1;
    const int lc0 = (t & 1) * 4;
    const unsigned sro = (unsigned)(lrow * 144 + lc0 * 16);

    float acc[2][8][4];
#pragma unroll
    for (int i = 0; i < 2; i++)
#pragma unroll
        for (int j = 0; j < 8; j++)
#pragma unroll
            for (int p = 0; p < 4; p++) acc[i][j][p] = 0.f;

    const int NS = kLen >> 6;

#define HG_LOAD(s) do { \
    unsigned _b = uS + (unsigned)((s) & 1) * HG_STAGE; \
    int _k = ((s) << 6) + lc0 * 8; \
    const __half* _pa = gA + (size_t)lrow * Kld + _k; \
    const __half* _pb = gB + (size_t)lrow * Kld + _k; \
    CP16(_b + sro,               _pa); \
    CP16(_b + sro + 16,          _pa + 8); \
    CP16(_b + sro + 32,          _pa + 16); \
    CP16(_b + sro + 48,          _pa + 24); \
    CP16(_b + 18432 + sro,       _pb); \
    CP16(_b + 18432 + sro + 16,  _pb + 8); \
    CP16(_b + 18432 + sro + 32,  _pb + 16); \
    CP16(_b + 18432 + sro + 48,  _pb + 24); \
    CPCOMMIT(); \
} while (0)

    HG_LOAD(0);

    for (int s = 0; s < NS; s++) {
        CPWAIT_0();
        __syncthreads();
        if (s + 1 < NS) HG_LOAD(s + 1);
        unsigned base = uS + (unsigned)(s & 1) * HG_STAGE;
#pragma unroll
        for (int kk = 0; kk < 64; kk += 16) {
            uint32_t af[2][4], bf[4][4];
#pragma unroll
            for (int mt = 0; mt < 2; mt++) {
                unsigned ra = base + (unsigned)((warpM + (mt << 4) + (lane & 15)) * 144 + ((kk + ((lane >> 4) << 3)) << 1));
                LDSM4(af[mt], ra);
            }
#pragma unroll
            for (int bj = 0; bj < 4; bj++) {
                unsigned rb = base + 18432u + (unsigned)((warpN + (bj << 4) + ((lane >> 4) << 3) + (lane & 7)) * 144 + ((kk + (((lane >> 3) & 1) << 3)) << 1));
                LDSM4(bf[bj], rb);
            }
#pragma unroll
            for (int mt = 0; mt < 2; mt++)
#pragma unroll
                for (int nt = 0; nt < 8; nt++) {
                    uint32_t b0 = bf[nt >> 1][(nt & 1) << 1];
                    uint32_t b1 = bf[nt >> 1][((nt & 1) << 1) + 1];
                    HMMA16816(acc[mt][nt], af[mt], b0, b1);
                }
        }
    }
#undef HG_LOAD

    const float sc = SCALED ? g_scale[slot] : 1.f;
#pragma unroll
    for (int mt = 0; mt < 2; mt++)
#pragma unroll
        for (int nt = 0; nt < 8; nt++) {
            int row = bm + warpM + (mt << 4) + (lane >> 2);
            int col = bn + warpN + (nt << 3) + ((lane & 3) << 1);
#pragma unroll
            for (int half = 0; half < 2; half++) {
                int r = row + half * 8;
                float v0 = acc[mt][nt][half * 2 + 0];
                float v1 = acc[mt][nt][half * 2 + 1];
                if (SCALED) { v0 *= sc; v1 *= sc; }
                if (bias) { v0 += bias[col]; v1 += bias[col + 1]; }
                if (RELU) { v0 = fmaxf(v0, 0.f); v1 = fmaxf(v1, 0.f); }
                if (OUT_F16) {
                    C16[(size_t)r * N + col]     = __float2half(v0);
                    C16[(size_t)r * N + col + 1] = __float2half(v1);
                } else {
                    C[(size_t)r * N + col]     = v0;
                    C[(size_t)r * N + col + 1] = v1;
                }
            }
        }
}

// ---------------- fused split-K(2) reduce + residual + LayerNorm (+fp16 out) ----------------
__global__ void ln_red(const float* __restrict__ bias, float* __restrict__ x,
                       __half* __restrict__ o16,
                       const float* __restrict__ gamma, const float* __restrict__ beta)
{
    __shared__ float sred[256];
    const int row = blockIdx.x, t = threadIdx.x;
    const size_t off = (size_t)row * DD;
    float4 p0 = ((const float4*)(g_psum + off))[t];
    float4 p1 = ((const float4*)(g_psum + MMDD + off))[t];
    float4 bb = ((const float4*)bias)[t];
    float4 rr = ((const float4*)(x + off))[t];
    float4 v;
    v.x = (p0.x + p1.x) + bb.x + rr.x;
    v.y = (p0.y + p1.y) + bb.y + rr.y;
    v.z = (p0.z + p1.z) + bb.z + rr.z;
    v.w = (p0.w + p1.w) + bb.w + rr.w;

    sred[t] = v.x + v.y + v.z + v.w;
    __syncthreads();
#pragma unroll
    for (int o = 128; o > 0; o >>= 1) { if (t < o) sred[t] += sred[t + o]; __syncthreads(); }
    float mean = sred[0] * (1.f / 1024.f);
    __syncthreads();
    float dx = v.x - mean, dy = v.y - mean, dz = v.z - mean, dw = v.w - mean;
    sred[t] = dx * dx + dy * dy + dz * dz + dw * dw;
    __syncthreads();
#pragma unroll
    for (int o = 128; o > 0; o >>= 1) { if (t < o) sred[t] += sred[t + o]; __syncthreads(); }
    float rstd = rsqrtf(sred[0] * (1.f / 1024.f) + EPSLN);
    float4 g = ((const float4*)gamma)[t];
    float4 b = ((const float4*)beta)[t];
    float4 o4;
    o4.x = dx * rstd * g.x + b.x;
    o4.y = dy * rstd * g.y + b.y;
    o4.z = dz * rstd * g.z + b.z;
    o4.w = dw * rstd * g.w + b.w;
    ((float4*)(x + off))[t] = o4;
    ushort4 h;
    h.x = f16bits(o4.x); h.y = f16bits(o4.y); h.z = f16bits(o4.z); h.w = f16bits(o4.w);
    ((ushort4*)(o16 + off))[t] = h;
}

// ---------------- final LayerNorm (fp16 out) ----------------
__global__ void ln_final(const float* __restrict__ in, __half* __restrict__ o16,
                         const float* __restrict__ gamma, const float* __restrict__ beta)
{
    __shared__ float sred[256];
    const int row = blockIdx.x, t = threadIdx.x;
    const float4 v = ((const float4*)(in + (size_t)row * DD))[t];
    sred[t] = v.x + v.y + v.z + v.w;
    __syncthreads();
#pragma unroll
    for (int o = 128; o > 0; o >>= 1) { if (t < o) sred[t] += sred[t + o]; __syncthreads(); }
    float mean = sred[0] * (1.f / 1024.f);
    __syncthreads();
    float dx = v.x - mean, dy = v.y - mean, dz = v.z - mean, dw = v.w - mean;
    sred[t] = dx * dx + dy * dy + dz * dz + dw * dw;
    __syncthreads();
#pragma unroll
    for (int o = 128; o > 0; o >>= 1) { if (t < o) sred[t] += sred[t + o]; __syncthreads(); }
    float rstd = rsqrtf(sred[0] * (1.f / 1024.f) + EPSLN);
    float4 g = ((const float4*)gamma)[t];
    float4 b = ((const float4*)beta)[t];
    ushort4 h;
    h.x = f16bits(dx * rstd * g.x + b.x);
    h.y = f16bits(dy * rstd * g.y + b.y);
    h.z = f16bits(dz * rstd * g.z + b.z);
    h.w = f16bits(dw * rstd * g.w + b.w);
    ((ushort4*)(o16 + (size_t)row * DD))[t] = h;
}

// ---------------- flag-array grid barrier ----------------
__device__ __forceinline__ void gbarf(unsigned k) {
    __syncthreads();
    if (threadIdx.x == 0) {
        __threadfence();
        g_flags[(unsigned)blockIdx.x * 32] = k;
    }
    if (threadIdx.x < GRU_CTAS) {
        while (g_flags[(unsigned)threadIdx.x * 32] < k) { }
    }
    __syncthreads();
}

// ---------------- persistent GRU ----------------
__global__ __launch_bounds__(192, 1) void gru_kernel(
    const float* __restrict__ gi, const float* __restrict__ whh,
    const float* __restrict__ bhh, float* __restrict__ x,
    __half* __restrict__ x16)
{
    __shared__ float hs[2048];
    __shared__ float sgh[48];
    __shared__ float sbh[24];
    const int tid = threadIdx.x;
    const int base = blockIdx.x * 8;
    const int r = tid >> 3, j = tid & 7;
    const int gg = r >> 3, ddim = r & 7;

    float4 wreg[32];
    const float* wrow = whh + (size_t)(gg * 1024 + base + ddim) * 1024;
#pragma unroll
    for (int i = 0; i < 32; i++)
        wreg[i] = *(const float4*)(wrow + (i * 8 + j) * 4);

    if (tid < 24) sbh[tid] = bhh[(tid >> 3) * 1024 + base + (tid & 7)];
    if (tid < 16) {
        int b = tid & 1, d0 = base + (tid >> 1);
        g_h[0][2 * d0 + b] = 0.f;
    }
    gbarf(1);

    for (int s = 0; s < SS; s++) {
        const int rb = s & 1, wb = rb ^ 1;

        float ir = 0.f, iz = 0.f, inn = 0.f;
        if (tid < 16) {
            int b = tid & 1, d0 = tid >> 1;
            int dg = base + d0;
            const float* gim = gi + ((size_t)b * SS + s) * 3072;
            ir  = __ldcg(gim + dg);
            iz  = __ldcg(gim + 1024 + dg);
            inn = __ldcg(gim + 2048 + dg);
        }

        for (int idx = tid; idx < 512; idx += 192)
            ((float4*)hs)[idx] = __ldcg((const float4*)&g_h[rb][0] + idx);
        __syncthreads();

        unsigned long long ac0 = 0ull, ac1 = 0ull, ac2 = 0ull, ac3 = 0ull;
#pragma unroll
        for (int i = 0; i < 32; i++) {
            int c4 = i * 8 + j;
            float4 hA = ((const float4*)hs)[c4 * 2];
            float4 hB = ((const float4*)hs)[c4 * 2 + 1];
            float4 w = wreg[i];
            ffma2(ac0, pk2(w.x, w.x), pk2(hA.x, hA.y));
            ffma2(ac1, pk2(w.y, w.y), pk2(hA.z, hA.w));
            ffma2(ac2, pk2(w.z, w.z), pk2(hB.x, hB.y));
            ffma2(ac3, pk2(w.w, w.w), pk2(hB.z, hB.w));
        }
        float2 s0 = unpk(ac0), s1 = unpk(ac1), s2 = unpk(ac2), s3 = unpk(ac3);
        float acc0 = (s0.x + s1.x) + (s2.x + s3.x);
        float acc1 = (s0.y + s1.y) + (s2.y + s3.y);
#pragma unroll
        for (int o = 4; o; o >>= 1) {
            acc0 += __shfl_down_sync(0xffffffffu, acc0, o);
            acc1 += __shfl_down_sync(0xffffffffu, acc1, o);
        }
        if (j == 0) { sgh[r * 2] = acc0 + sbh[r]; sgh[r * 2 + 1] = acc1 + sbh[r]; }
        __syncthreads();

        if (tid < 16) {
            int b = tid & 1, d0 = tid >> 1;
            int dg = base + d0;
            float hr = sgh[d0 * 2 + b], hz = sgh[(8 + d0) * 2 + b], hn = sgh[(16 + d0) * 2 + b];
            float rg = 1.f / (1.f + expf(-(ir + hr)));
            float zg = 1.f / (1.f + expf(-(iz + hz)));
            float ng = tanhf(inn + rg * hn);
            float hp = hs[2 * dg + b];
            float hv = (1.f - zg) * ng + zg * hp;
            __stcg(&g_h[wb][2 * dg + b], hv);
            size_t m = (size_t)b * SS + s;
            x[m * 1024 + dg] = hv;
            x16[m * 1024 + dg] = __float2half(hv);
        }
        if (s + 1 < SS) gbarf(2 + s);
    }

    if (tid == 0) {
        __threadfence();
        unsigned a = atomicAdd(&g_ack, 1u);
        if (a == GRU_CTAS - 1) {
            for (int i = 0; i < GRU_CTAS; i++) g_flags[i * 32] = 0;
            __threadfence();
            g_ack = 0;
            __threadfence();
        }
    }
}

// ---------------- launch ----------------
extern "C" void kernel_launch(void* const* d_in, const int* in_sizes, int n_in,
                              void* d_out, int out_size) {
    const int*   ids     = (const int*)  d_in[0];
    const float* emb     = (const float*)d_in[1];
    const float* pos     = (const float*)d_in[2];
    const float* gru_wih = (const float*)d_in[3];
    const float* gru_whh = (const float*)d_in[4];
    const float* gru_bih = (const float*)d_in[5];
    const float* gru_bhh = (const float*)d_in[6];
    const float* syn_w   = (const float*)d_in[7];
    const float* syn_b   = (const float*)d_in[8];
    const float* out_w   = (const float*)d_in[9];
    const float* out_b   = (const float*)d_in[10];
    const float* ln_g    = (const float*)d_in[11];
    const float* ln_b    = (const float*)d_in[12];
    const float* on_g    = (const float*)d_in[13];
    const float* on_b    = (const float*)d_in[14];
    const float* head_w  = (const float*)d_in[15];
    const float* head_b  = (const float*)d_in[16];
    float* logits = (float*)d_out;

    float *xg, *gig, *psg;
    __half *w16ih, *q16syn, *q16out, *q16head, *x16, *h16, *y16;
    cudaGetSymbolAddress((void**)&xg,   g_x);
    cudaGetSymbolAddress((void**)&gig,  g_gi);
    cudaGetSymbolAddress((void**)&psg,  g_psum);
    cudaGetSymbolAddress((void**)&w16ih,  g_w16ih);
    cudaGetSymbolAddress((void**)&q16syn,  g_q16syn);
    cudaGetSymbolAddress((void**)&q16out,  g_q16out);
    cudaGetSymbolAddress((void**)&q16head, g_q16head);
    cudaGetSymbolAddress((void**)&x16, g_x16);
    cudaGetSymbolAddress((void**)&h16, g_h16);
    cudaGetSymbolAddress((void**)&y16, g_y16);

    static cudaStream_t s1, s2;
    static cudaEvent_t evRoot, ev1, ev2;
    static bool init_done = false;
    if (!init_done) {
        cudaFuncSetAttribute(hgemm<true,  true,  true >, cudaFuncAttributeMaxDynamicSharedMemorySize, HG_SMEM);
        cudaFuncSetAttribute(hgemm<false, false, true >, cudaFuncAttributeMaxDynamicSharedMemorySize, HG_SMEM);
        cudaFuncSetAttribute(hgemm<false, false, false>, cudaFuncAttributeMaxDynamicSharedMemorySize, HG_SMEM);
        cudaStreamCreateWithFlags(&s1, cudaStreamNonBlocking);
        cudaStreamCreateWithFlags(&s2, cudaStreamNonBlocking);
        cudaEventCreateWithFlags(&evRoot, cudaEventDisableTiming);
        cudaEventCreateWithFlags(&ev1, cudaEventDisableTiming);
        cudaEventCreateWithFlags(&ev2, cudaEventDisableTiming);
        init_done = true;
    }

    long nVD4 = (long)VV * DD / 4, nND4 = (long)NNH * DD / 4;

    // main stream first: launch #4 = in-proj hgemm (ncu capture target)
    absmean_part<<<512, 256>>>((const float4*)emb, nVD4, 0);
    absmean_final<<<1, 256>>>(0);
    embed_kernel<<<4096, 256>>>(ids, emb, pos, y16, gru_wih, w16ih);
    hgemm<false, false, false><<<dim3(3072 / 128, MROWS / 128, 1), 256, HG_SMEM>>>(
        y16, w16ih, gig, (__half*)0, gru_bih, MROWS, 3072, DD, DD, 0);
    gru_kernel<<<GRU_CTAS, 192>>>(gig, gru_whh, gru_bhh, xg, x16);

    cudaEventRecord(evRoot, 0);
    cudaStreamWaitEvent(s1, evRoot, 0);
    cudaStreamWaitEvent(s2, evRoot, 0);

    // side stream 1: layer weight scales + fp16 quantization
    for (int l = 0; l < 4; l++) {
        absmean_part<<<512, 256, 0, s1>>>((const float4*)(syn_w + (size_t)l * NNH * DD), nND4, 2 + l);
        absmean_part<<<512, 256, 0, s1>>>((const float4*)(out_w + (size_t)l * DD * NNH), nND4, 6 + l);
    }
    absmean_final<<<8, 256, 0, s1>>>(2);
    for (int l = 0; l < 4; l++) {
        tern_quant16<<<(int)(nND4 / 256), 256, 0, s1>>>((const float4*)(syn_w + (size_t)l * NNH * DD),
                                                        (ushort4*)(q16syn + (size_t)l * NNH * DD), 2 + l, (int)nND4);
        tern_quant16<<<(int)(nND4 / 256), 256, 0, s1>>>((const float4*)(out_w + (size_t)l * DD * NNH),
                                                        (ushort4*)(q16out + (size_t)l * DD * NNH), 6 + l, (int)nND4);
    }
    cudaEventRecord(ev1, s1);

    // side stream 2: head scale + fp16 quantization
    absmean_part<<<512, 256, 0, s2>>>((const float4*)head_w, nVD4, 1);
    absmean_final<<<1, 256, 0, s2>>>(1);
    tern_quant16<<<(int)(nVD4 / 256), 256, 0, s2>>>((const float4*)head_w, (ushort4*)q16head, 1, (int)nVD4);
    cudaEventRecord(ev2, s2);

    // join layer-weight stream, MLP (single-pass fp16, split-K=2)
    cudaStreamWaitEvent(0, ev1, 0);
    for (int l = 0; l < 4; l++) {
        hgemm<true, true, true><<<dim3(NNH / 128, MROWS / 128, 1), 256, HG_SMEM>>>(
            x16, q16syn + (size_t)l * NNH * DD, (float*)0, h16,
            syn_b + (size_t)l * NNH, MROWS, NNH, DD, DD, 2 + l);
        hgemm<false, false, true><<<dim3(DD / 128, MROWS / 128, 2), 256, HG_SMEM>>>(
            h16, q16out + (size_t)l * DD * NNH, psg, (__half*)0,
            (const float*)0, MROWS, DD, NNH, NNH / 2, 6 + l);
        ln_red<<<MROWS, 256>>>(out_b + (size_t)l * DD, xg, x16,
                               ln_g + (size_t)l * DD, ln_b + (size_t)l * DD);
    }

    // join head stream, final LN + head
    cudaStreamWaitEvent(0, ev2, 0);
    ln_final<<<MROWS, 256>>>(xg, y16, on_g, on_b);
    hgemm<false, false, true><<<dim3(VV / 128, MROWS / 128, 1), 256, HG_SMEM>>>(
        y16, q16head, logits, (__half*)0, head_b, MROWS, VV, DD, DD, 1);
}

// round 15
// speedup vs baseline: 1.0228x; 1.0228x over previous
#include <cuda_runtime.h>
#include <cuda_bf16.h>
#include <cuda_fp16.h>
#include <math.h>
#include <stdint.h>
#include <stddef.h>

#define SS 512
#define DD 1024
#define NNH 4096
#define VV 32000
#define MROWS 1024
#define MMDD (MROWS * DD)
#define EPSLN 1e-5f
#define GRU_CTAS 128

// ---------------- device scratch ----------------
__device__ float  g_x[MROWS * DD];
__device__ float  g_gi[MROWS * 3 * DD];
__device__ float  g_psum[2 * MROWS * DD];
__device__ float  g_h[2][2 * DD];
__device__ double g_part[10 * 512];
__device__ float  g_scale[10];
__device__ float  g_scaleinv[10];
__device__ volatile unsigned g_flags[GRU_CTAS * 32];
__device__ unsigned g_ack;

// fp16 buffers
__device__ __half g_w16ih[3 * DD * DD];
__device__ __half g_q16syn[4 * NNH * DD];
__device__ __half g_q16out[4 * NNH * DD];
__device__ __half g_q16head[VV * DD];
__device__ __half g_x16[MROWS * DD];
__device__ __half g_h16[MROWS * NNH];
__device__ __half g_y16[MROWS * DD];

// ---------------- asm helpers ----------------
#define CP16(dst, src) asm volatile("cp.async.cg.shared.global [%0], [%1], 16;" :: "r"(dst), "l"(src))
#define CPCOMMIT() asm volatile("cp.async.commit_group;")
#define CPWAIT_1() asm volatile("cp.async.wait_group 1;")
#define LDSM4(r, addr) asm volatile( \
    "ldmatrix.sync.aligned.m8n8.x4.shared.b16 {%0,%1,%2,%3}, [%4];" \
    : "=r"((r)[0]), "=r"((r)[1]), "=r"((r)[2]), "=r"((r)[3]) : "r"(addr))
#define HMMA16816(d, a, b0, b1) asm volatile( \
    "mma.sync.aligned.m16n8k16.row.col.f32.f16.f16.f32 " \
    "{%0,%1,%2,%3},{%4,%5,%6,%7},{%8,%9},{%0,%1,%2,%3};" \
    : "+f"((d)[0]), "+f"((d)[1]), "+f"((d)[2]), "+f"((d)[3]) \
    : "r"((a)[0]), "r"((a)[1]), "r"((a)[2]), "r"((a)[3]), "r"(b0), "r"(b1))

__device__ __forceinline__ unsigned short f16bits(float x) {
    return __half_as_ushort(__float2half(x));
}
__device__ __forceinline__ unsigned long long pk2(float x, float y) {
    unsigned long long r;
    asm("mov.b64 %0, {%1, %2};" : "=l"(r) : "f"(x), "f"(y));
    return r;
}
__device__ __forceinline__ void ffma2(unsigned long long& d, unsigned long long a, unsigned long long b) {
    asm("fma.rn.f32x2 %0, %1, %2, %0;" : "+l"(d) : "l"(a), "l"(b));
}
__device__ __forceinline__ float2 unpk(unsigned long long v) {
    float2 f;
    asm("mov.b64 {%0, %1}, %2;" : "=f"(f.x), "=f"(f.y) : "l"(v));
    return f;
}

// ---------------- abs-mean scale ----------------
__global__ __launch_bounds__(256, 2) void absmean_part(const float4* __restrict__ src, long n4, int slot) {
    __shared__ double sred[256];
    double a[8];
#pragma unroll
    for (int c = 0; c < 8; c++) a[c] = 0.0;
    const long stride = (long)gridDim.x * 256;
    long i = (long)blockIdx.x * 256 + threadIdx.x;
    for (; i + 7 * stride < n4; i += 8 * stride) {
        float4 v[8];
#pragma unroll
        for (int c = 0; c < 8; c++) v[c] = src[i + c * stride];
#pragma unroll
        for (int c = 0; c < 8; c++)
            a[c] += (double)(fabsf(v[c].x) + fabsf(v[c].y)) + (double)(fabsf(v[c].z) + fabsf(v[c].w));
    }
    for (; i < n4; i += stride) {
        float4 v = src[i];
        a[0] += (double)(fabsf(v.x) + fabsf(v.y)) + (double)(fabsf(v.z) + fabsf(v.w));
    }
    sred[threadIdx.x] = ((a[0] + a[1]) + (a[2] + a[3])) + ((a[4] + a[5]) + (a[6] + a[7]));
    __syncthreads();
#pragma unroll
    for (int o = 128; o > 0; o >>= 1) {
        if ((int)threadIdx.x < o) sred[threadIdx.x] += sred[threadIdx.x + o];
        __syncthreads();
    }
    if (threadIdx.x == 0) g_part[slot * 512 + blockIdx.x] = sred[0];
}

__global__ void absmean_final(int base) {
    __shared__ double sred[256];
    int slot = base + blockIdx.x, t = threadIdx.x;
    sred[t] = g_part[slot * 512 + t] + g_part[slot * 512 + 256 + t];
    __syncthreads();
#pragma unroll
    for (int o = 128; o > 0; o >>= 1) {
        if (t < o) sred[t] += sred[t + o];
        __syncthreads();
    }
    if (t == 0) {
        double cnt = (slot < 2) ? (double)VV * DD : (double)NNH * DD;
        double s = sred[0] / cnt + 1e-8;
        g_scale[slot]    = (float)s;
        g_scaleinv[slot] = (float)(1.0 / s);
    }
}

// ---------------- weight conversion ----------------
__global__ void tern_quant16(const float4* __restrict__ w, ushort4* __restrict__ q,
                             int slot, int n4) {
    int i = blockIdx.x * 256 + threadIdx.x;
    if (i >= n4) return;
    float inv = g_scaleinv[slot];
    float4 v = w[i];
    ushort4 o;
    o.x = f16bits(rintf(fminf(fmaxf(v.x * inv, -1.f), 1.f)));
    o.y = f16bits(rintf(fminf(fmaxf(v.y * inv, -1.f), 1.f)));
    o.z = f16bits(rintf(fminf(fmaxf(v.z * inv, -1.f), 1.f)));
    o.w = f16bits(rintf(fminf(fmaxf(v.w * inv, -1.f), 1.f)));
    q[i] = o;
}

// ---------------- embedding (fp16 out) + fused wih fp16 conversion ----------------
__global__ void embed_kernel(const int* __restrict__ ids, const float* __restrict__ emb,
                             const float* __restrict__ pos, __half* __restrict__ e16,
                             const float* __restrict__ wih, __half* __restrict__ w16) {
    int i = blockIdx.x * 256 + threadIdx.x;
    int d = i & (DD - 1);
    int s = (i >> 10) & (SS - 1);
    int b = i >> 19;
    int tok = ids[b * SS + s];
    float w = emb[(size_t)tok * DD + d];
    float tn = g_scale[0] * rintf(fminf(fmaxf(w * g_scaleinv[0], -1.f), 1.f));
    e16[i] = __float2half(tn + pos[s * DD + d]);
    w16[i]            = __float2half(wih[i]);
    w16[i + MMDD]     = __float2half(wih[i + MMDD]);
    w16[i + 2 * MMDD] = __float2half(wih[i + 2 * MMDD]);
}

// ---------------- single-pass FP16 GEMM NT, 3-stage cp.async (R11 config) ----------------
#define HG_STAGE 20480
#define HG_SMEM (3 * HG_STAGE)         // 61440 B

template<bool RELU, bool OUT_F16, bool SCALED>
__global__ __launch_bounds__(256) void hgemm(
    const __half* __restrict__ A, const __half* __restrict__ B,
    float* __restrict__ C, __half* __restrict__ C16,
    const float* __restrict__ bias,
    int M, int N, int Kld, int kLen, int slot)
{
    extern __shared__ __align__(16) __half smh[];
    const int t = threadIdx.x;
    const int lane = t & 31;
    const int w = t >> 5;
    const int warpM = (w >> 1) << 5;
    const int warpN = (w & 1) << 6;
    const int bm = blockIdx.y << 7, bn = blockIdx.x << 7;
    const int kOff = blockIdx.z * kLen;
    if (gridDim.z > 1) C += (size_t)blockIdx.z * ((size_t)M * N);

    const __half* gA = A + (size_t)bm * Kld + kOff;
    const __half* gB = B + (size_t)bn * Kld + kOff;
    const unsigned uS = (unsigned)__cvta_generic_to_shared(smh);

    const int lrow = t >> 2;
    const int lcol = (t & 3) << 3;
    const unsigned wro = (unsigned)(lrow * 80 + lcol * 2);

    float acc[2][8][4];
#pragma unroll
    for (int i = 0; i < 2; i++)
#pragma unroll
        for (int j = 0; j < 8; j++)
#pragma unroll
            for (int p = 0; p < 4; p++) acc[i][j][p] = 0.f;

    const int NS = kLen >> 5;

#define HG_LOAD(s) do { \
    unsigned _b = uS + (unsigned)((s) % 3) * HG_STAGE; \
    int _k = (s) << 5; \
    CP16(_b + wro,                     gA + (size_t)lrow * Kld + _k + lcol); \
    CP16(_b + wro + 64 * 80,           gA + (size_t)(lrow + 64) * Kld + _k + lcol); \
    CP16(_b + 10240 + wro,             gB + (size_t)lrow * Kld + _k + lcol); \
    CP16(_b + 10240 + wro + 64 * 80,   gB + (size_t)(lrow + 64) * Kld + _k + lcol); \
    CPCOMMIT(); \
} while (0)

    HG_LOAD(0);
    if (NS > 1) HG_LOAD(1); else CPCOMMIT();

    for (int s = 0; s < NS; s++) {
        CPWAIT_1();
        __syncthreads();
        unsigned base = uS + (unsigned)(s % 3) * HG_STAGE;
#pragma unroll
        for (int kk = 0; kk < 32; kk += 16) {
            uint32_t af[2][4], bf[4][4];
#pragma unroll
            for (int mt = 0; mt < 2; mt++) {
                unsigned ra = base + (unsigned)((warpM + (mt << 4) + (lane & 15)) * 80 + ((kk + ((lane >> 4) << 3)) << 1));
                LDSM4(af[mt], ra);
            }
#pragma unroll
            for (int bj = 0; bj < 4; bj++) {
                unsigned rb = base + 10240u + (unsigned)((warpN + (bj << 4) + ((lane >> 4) << 3) + (lane & 7)) * 80 + ((kk + (((lane >> 3) & 1) << 3)) << 1));
                LDSM4(bf[bj], rb);
            }
#pragma unroll
            for (int mt = 0; mt < 2; mt++)
#pragma unroll
                for (int nt = 0; nt < 8; nt++) {
                    uint32_t b0 = bf[nt >> 1][(nt & 1) << 1];
                    uint32_t b1 = bf[nt >> 1][((nt & 1) << 1) + 1];
                    HMMA16816(acc[mt][nt], af[mt], b0, b1);
                }
        }
        if (s + 2 < NS) HG_LOAD(s + 2); else CPCOMMIT();
    }
#undef HG_LOAD

    const float sc = SCALED ? g_scale[slot] : 1.f;
#pragma unroll
    for (int mt = 0; mt < 2; mt++)
#pragma unroll
        for (int nt = 0; nt < 8; nt++) {
            int row = bm + warpM + (mt << 4) + (lane >> 2);
            int col = bn + warpN + (nt << 3) + ((lane & 3) << 1);
#pragma unroll
            for (int half = 0; half < 2; half++) {
                int r = row + half * 8;
                float v0 = acc[mt][nt][half * 2 + 0];
                float v1 = acc[mt][nt][half * 2 + 1];
                if (SCALED) { v0 *= sc; v1 *= sc; }
                if (bias) { v0 += bias[col]; v1 += bias[col + 1]; }
                if (RELU) { v0 = fmaxf(v0, 0.f); v1 = fmaxf(v1, 0.f); }
                if (OUT_F16) {
                    C16[(size_t)r * N + col]     = __float2half(v0);
                    C16[(size_t)r * N + col + 1] = __float2half(v1);
                } else {
                    C[(size_t)r * N + col]     = v0;
                    C[(size_t)r * N + col + 1] = v1;
                }
            }
        }
}

// ---------------- fused split-K(2) reduce + residual + LayerNorm (+fp16 out) ----------------
__global__ void ln_red(const float* __restrict__ bias, float* __restrict__ x,
                       __half* __restrict__ o16,
                       const float* __restrict__ gamma, const float* __restrict__ beta)
{
    __shared__ float sred[256];
    const int row = blockIdx.x, t = threadIdx.x;
    const size_t off = (size_t)row * DD;
    float4 p0 = ((const float4*)(g_psum + off))[t];
    float4 p1 = ((const float4*)(g_psum + MMDD + off))[t];
    float4 bb = ((const float4*)bias)[t];
    float4 rr = ((const float4*)(x + off))[t];
    float4 v;
    v.x = (p0.x + p1.x) + bb.x + rr.x;
    v.y = (p0.y + p1.y) + bb.y + rr.y;
    v.z = (p0.z + p1.z) + bb.z + rr.z;
    v.w = (p0.w + p1.w) + bb.w + rr.w;

    sred[t] = v.x + v.y + v.z + v.w;
    __syncthreads();
#pragma unroll
    for (int o = 128; o > 0; o >>= 1) { if (t < o) sred[t] += sred[t + o]; __syncthreads(); }
    float mean = sred[0] * (1.f / 1024.f);
    __syncthreads();
    float dx = v.x - mean, dy = v.y - mean, dz = v.z - mean, dw = v.w - mean;
    sred[t] = dx * dx + dy * dy + dz * dz + dw * dw;
    __syncthreads();
#pragma unroll
    for (int o = 128; o > 0; o >>= 1) { if (t < o) sred[t] += sred[t + o]; __syncthreads(); }
    float rstd = rsqrtf(sred[0] * (1.f / 1024.f) + EPSLN);
    float4 g = ((const float4*)gamma)[t];
    float4 b = ((const float4*)beta)[t];
    float4 o4;
    o4.x = dx * rstd * g.x + b.x;
    o4.y = dy * rstd * g.y + b.y;
    o4.z = dz * rstd * g.z + b.z;
    o4.w = dw * rstd * g.w + b.w;
    ((float4*)(x + off))[t] = o4;
    ushort4 h;
    h.x = f16bits(o4.x); h.y = f16bits(o4.y); h.z = f16bits(o4.z); h.w = f16bits(o4.w);
    ((ushort4*)(o16 + off))[t] = h;
}

// ---------------- final LayerNorm (fp16 out) ----------------
__global__ void ln_final(const float* __restrict__ in, __half* __restrict__ o16,
                         const float* __restrict__ gamma, const float* __restrict__ beta)
{
    __shared__ float sred[256];
    const int row = blockIdx.x, t = threadIdx.x;
    const float4 v = ((const float4*)(in + (size_t)row * DD))[t];
    sred[t] = v.x + v.y + v.z + v.w;
    __syncthreads();
#pragma unroll
    for (int o = 128; o > 0; o >>= 1) { if (t < o) sred[t] += sred[t + o]; __syncthreads(); }
    float mean = sred[0] * (1.f / 1024.f);
    __syncthreads();
    float dx = v.x - mean, dy = v.y - mean, dz = v.z - mean, dw = v.w - mean;
    sred[t] = dx * dx + dy * dy + dz * dz + dw * dw;
    __syncthreads();
#pragma unroll
    for (int o = 128; o > 0; o >>= 1) { if (t < o) sred[t] += sred[t + o]; __syncthreads(); }
    float rstd = rsqrtf(sred[0] * (1.f / 1024.f) + EPSLN);
    float4 g = ((const float4*)gamma)[t];
    float4 b = ((const float4*)beta)[t];
    ushort4 h;
    h.x = f16bits(dx * rstd * g.x + b.x);
    h.y = f16bits(dy * rstd * g.y + b.y);
    h.z = f16bits(dz * rstd * g.z + b.z);
    h.w = f16bits(dw * rstd * g.w + b.w);
    ((ushort4*)(o16 + (size_t)row * DD))[t] = h;
}

// ---------------- flag-array grid barrier ----------------
__device__ __forceinline__ void gbarf(unsigned k) {
    __syncthreads();
    if (threadIdx.x == 0) {
        __threadfence();
        g_flags[(unsigned)blockIdx.x * 32] = k;
    }
    if (threadIdx.x < GRU_CTAS) {
        while (g_flags[(unsigned)threadIdx.x * 32] < k) { }
    }
    __syncthreads();
}

// ---------------- persistent GRU ----------------
__global__ __launch_bounds__(192, 1) void gru_kernel(
    const float* __restrict__ gi, const float* __restrict__ whh,
    const float* __restrict__ bhh, float* __restrict__ x,
    __half* __restrict__ x16)
{
    __shared__ float hs[2048];
    __shared__ float sgh[48];
    __shared__ float sbh[24];
    const int tid = threadIdx.x;
    const int base = blockIdx.x * 8;
    const int r = tid >> 3, j = tid & 7;
    const int gg = r >> 3, ddim = r & 7;

    float4 wreg[32];
    const float* wrow = whh + (size_t)(gg * 1024 + base + ddim) * 1024;
#pragma unroll
    for (int i = 0; i < 32; i++)
        wreg[i] = *(const float4*)(wrow + (i * 8 + j) * 4);

    if (tid < 24) sbh[tid] = bhh[(tid >> 3) * 1024 + base + (tid & 7)];
    if (tid < 16) {
        int b = tid & 1, d0 = base + (tid >> 1);
        g_h[0][2 * d0 + b] = 0.f;
    }
    gbarf(1);

    for (int s = 0; s < SS; s++) {
        const int rb = s & 1, wb = rb ^ 1;

        float ir = 0.f, iz = 0.f, inn = 0.f;
        if (tid < 16) {
            int b = tid & 1, d0 = tid >> 1;
            int dg = base + d0;
            const float* gim = gi + ((size_t)b * SS + s) * 3072;
            ir  = __ldcg(gim + dg);
            iz  = __ldcg(gim + 1024 + dg);
            inn = __ldcg(gim + 2048 + dg);
        }

        for (int idx = tid; idx < 512; idx += 192)
            ((float4*)hs)[idx] = __ldcg((const float4*)&g_h[rb][0] + idx);
        __syncthreads();

        unsigned long long ac0 = 0ull, ac1 = 0ull, ac2 = 0ull, ac3 = 0ull;
#pragma unroll
        for (int i = 0; i < 32; i++) {
            int c4 = i * 8 + j;
            float4 hA = ((const float4*)hs)[c4 * 2];
            float4 hB = ((const float4*)hs)[c4 * 2 + 1];
            float4 w = wreg[i];
            ffma2(ac0, pk2(w.x, w.x), pk2(hA.x, hA.y));
            ffma2(ac1, pk2(w.y, w.y), pk2(hA.z, hA.w));
            ffma2(ac2, pk2(w.z, w.z), pk2(hB.x, hB.y));
            ffma2(ac3, pk2(w.w, w.w), pk2(hB.z, hB.w));
        }
        float2 s0 = unpk(ac0), s1 = unpk(ac1), s2 = unpk(ac2), s3 = unpk(ac3);
        float acc0 = (s0.x + s1.x) + (s2.x + s3.x);
        float acc1 = (s0.y + s1.y) + (s2.y + s3.y);
#pragma unroll
        for (int o = 4; o; o >>= 1) {
            acc0 += __shfl_down_sync(0xffffffffu, acc0, o);
            acc1 += __shfl_down_sync(0xffffffffu, acc1, o);
        }
        if (j == 0) { sgh[r * 2] = acc0 + sbh[r]; sgh[r * 2 + 1] = acc1 + sbh[r]; }
        __syncthreads();

        if (tid < 16) {
            int b = tid & 1, d0 = tid >> 1;
            int dg = base + d0;
            float hr = sgh[d0 * 2 + b], hz = sgh[(8 + d0) * 2 + b], hn = sgh[(16 + d0) * 2 + b];
            float rg = 1.f / (1.f + expf(-(ir + hr)));
            float zg = 1.f / (1.f + expf(-(iz + hz)));
            float ng = tanhf(inn + rg * hn);
            float hp = hs[2 * dg + b];
            float hv = (1.f - zg) * ng + zg * hp;
            __stcg(&g_h[wb][2 * dg + b], hv);
            size_t m = (size_t)b * SS + s;
            x[m * 1024 + dg] = hv;
            x16[m * 1024 + dg] = __float2half(hv);
        }
        if (s + 1 < SS) gbarf(2 + s);
    }

    if (tid == 0) {
        __threadfence();
        unsigned a = atomicAdd(&g_ack, 1u);
        if (a == GRU_CTAS - 1) {
            for (int i = 0; i < GRU_CTAS; i++) g_flags[i * 32] = 0;
            __threadfence();
            g_ack = 0;
            __threadfence();
        }
    }
}

// ---------------- launch ----------------
extern "C" void kernel_launch(void* const* d_in, const int* in_sizes, int n_in,
                              void* d_out, int out_size) {
    const int*   ids     = (const int*)  d_in[0];
    const float* emb     = (const float*)d_in[1];
    const float* pos     = (const float*)d_in[2];
    const float* gru_wih = (const float*)d_in[3];
    const float* gru_whh = (const float*)d_in[4];
    const float* gru_bih = (const float*)d_in[5];
    const float* gru_bhh = (const float*)d_in[6];
    const float* syn_w   = (const float*)d_in[7];
    const float* syn_b   = (const float*)d_in[8];
    const float* out_w   = (const float*)d_in[9];
    const float* out_b   = (const float*)d_in[10];
    const float* ln_g    = (const float*)d_in[11];
    const float* ln_b    = (const float*)d_in[12];
    const float* on_g    = (const float*)d_in[13];
    const float* on_b    = (const float*)d_in[14];
    const float* head_w  = (const float*)d_in[15];
    const float* head_b  = (const float*)d_in[16];
    float* logits = (float*)d_out;

    float *xg, *gig, *psg;
    __half *w16ih, *q16syn, *q16out, *q16head, *x16, *h16, *y16;
    cudaGetSymbolAddress((void**)&xg,   g_x);
    cudaGetSymbolAddress((void**)&gig,  g_gi);
    cudaGetSymbolAddress((void**)&psg,  g_psum);
    cudaGetSymbolAddress((void**)&w16ih,  g_w16ih);
    cudaGetSymbolAddress((void**)&q16syn,  g_q16syn);
    cudaGetSymbolAddress((void**)&q16out,  g_q16out);
    cudaGetSymbolAddress((void**)&q16head, g_q16head);
    cudaGetSymbolAddress((void**)&x16, g_x16);
    cudaGetSymbolAddress((void**)&h16, g_h16);
    cudaGetSymbolAddress((void**)&y16, g_y16);

    static cudaStream_t s1, s2;
    static cudaEvent_t evRoot, ev1, ev2;
    static bool init_done = false;
    if (!init_done) {
        cudaFuncSetAttribute(hgemm<true,  true,  true >, cudaFuncAttributeMaxDynamicSharedMemorySize, HG_SMEM);
        cudaFuncSetAttribute(hgemm<false, false, true >, cudaFuncAttributeMaxDynamicSharedMemorySize, HG_SMEM);
        cudaFuncSetAttribute(hgemm<false, false, false>, cudaFuncAttributeMaxDynamicSharedMemorySize, HG_SMEM);
        cudaStreamCreateWithFlags(&s1, cudaStreamNonBlocking);
        cudaStreamCreateWithFlags(&s2, cudaStreamNonBlocking);
        cudaEventCreateWithFlags(&evRoot, cudaEventDisableTiming);
        cudaEventCreateWithFlags(&ev1, cudaEventDisableTiming);
        cudaEventCreateWithFlags(&ev2, cudaEventDisableTiming);
        init_done = true;
    }

    long nVD4 = (long)VV * DD / 4, nND4 = (long)NNH * DD / 4;

    // main stream first: launch #4 = in-proj hgemm (ncu capture target)
    absmean_part<<<512, 256>>>((const float4*)emb, nVD4, 0);
    absmean_final<<<1, 256>>>(0);
    embed_kernel<<<4096, 256>>>(ids, emb, pos, y16, gru_wih, w16ih);
    hgemm<false, false, false><<<dim3(3072 / 128, MROWS / 128, 1), 256, HG_SMEM>>>(
        y16, w16ih, gig, (__half*)0, gru_bih, MROWS, 3072, DD, DD, 0);
    gru_kernel<<<GRU_CTAS, 192>>>(gig, gru_whh, gru_bhh, xg, x16);

    cudaEventRecord(evRoot, 0);
    cudaStreamWaitEvent(s1, evRoot, 0);
    cudaStreamWaitEvent(s2, evRoot, 0);

    // side stream 1: layer weight scales + fp16 quantization
    for (int l = 0; l < 4; l++) {
        absmean_part<<<512, 256, 0, s1>>>((const float4*)(syn_w + (size_t)l * NNH * DD), nND4, 2 + l);
        absmean_part<<<512, 256, 0, s1>>>((const float4*)(out_w + (size_t)l * DD * NNH), nND4, 6 + l);
    }
    absmean_final<<<8, 256, 0, s1>>>(2);
    for (int l = 0; l < 4; l++) {
        tern_quant16<<<(int)(nND4 / 256), 256, 0, s1>>>((const float4*)(syn_w + (size_t)l * NNH * DD),
                                                        (ushort4*)(q16syn + (size_t)l * NNH * DD), 2 + l, (int)nND4);
        tern_quant16<<<(int)(nND4 / 256), 256, 0, s1>>>((const float4*)(out_w + (size_t)l * DD * NNH),
                                                        (ushort4*)(q16out + (size_t)l * DD * NNH), 6 + l, (int)nND4);
    }
    cudaEventRecord(ev1, s1);

    // side stream 2: head scale + fp16 quantization
    absmean_part<<<512, 256, 0, s2>>>((const float4*)head_w, nVD4, 1);
    absmean_final<<<1, 256, 0, s2>>>(1);
    tern_quant16<<<(int)(nVD4 / 256), 256, 0, s2>>>((const float4*)head_w, (ushort4*)q16head, 1, (int)nVD4);
    cudaEventRecord(ev2, s2);

    // join layer-weight stream, MLP (single-pass fp16, split-K=2)
    cudaStreamWaitEvent(0, ev1, 0);
    for (int l = 0; l < 4; l++) {
        hgemm<true, true, true><<<dim3(NNH / 128, MROWS / 128, 1), 256, HG_SMEM>>>(
            x16, q16syn + (size_t)l * NNH * DD, (float*)0, h16,
            syn_b + (size_t)l * NNH, MROWS, NNH, DD, DD, 2 + l);
        hgemm<false, false, true><<<dim3(DD / 128, MROWS / 128, 2), 256, HG_SMEM>>>(
            h16, q16out + (size_t)l * DD * NNH, psg, (__half*)0,
            (const float*)0, MROWS, DD, NNH, NNH / 2, 6 + l);
        ln_red<<<MROWS, 256>>>(out_b + (size_t)l * DD, xg, x16,
                               ln_g + (size_t)l * DD, ln_b + (size_t)l * DD);
    }

    // join head stream, final LN + head
    cudaStreamWaitEvent(0, ev2, 0);
    ln_final<<<MROWS, 256>>>(xg, y16, on_g, on_b);
    hgemm<false, false, true><<<dim3(VV / 128, MROWS / 128, 1), 256, HG_SMEM>>>(
        y16, q16head, logits, (__half*)0, head_b, MROWS, VV, DD, DD, 1);
}

// round 17
// speedup vs baseline: 1.0624x; 1.0388x over previous
#include <cuda_runtime.h>
#include <cuda_bf16.h>
#include <cuda_fp16.h>
#include <math.h>
#include <stdint.h>
#include <stddef.h>

#define SS 512
#define DD 1024
#define NNH 4096
#define VV 32000
#define MROWS 1024
#define MMDD (MROWS * DD)
#define EPSLN 1e-5f
#define GRU_CTAS 128

// ---------------- device scratch ----------------
__device__ float  g_x[MROWS * DD];
__device__ float  g_gi[MROWS * 3 * DD];
__device__ float  g_psum[2 * MROWS * DD];
__device__ float  g_h[2][2 * DD];
__device__ double g_part[10 * 512];
__device__ float  g_scale[10];
__device__ float  g_scaleinv[10];
__device__ volatile unsigned g_flags[GRU_CTAS * 32];
__device__ unsigned g_ack;

// fp16 buffers
__device__ __half g_w16ih[3 * DD * DD];
__device__ __half g_q16syn[4 * NNH * DD];
__device__ __half g_q16out[4 * NNH * DD];
__device__ __half g_q16head[VV * DD];
__device__ __half g_x16[MROWS * DD];
__device__ __half g_h16[MROWS * NNH];
__device__ __half g_y16[MROWS * DD];

// ---------------- asm helpers ----------------
#define CP16(dst, src) asm volatile("cp.async.cg.shared.global [%0], [%1], 16;" :: "r"(dst), "l"(src))
#define CPCOMMIT() asm volatile("cp.async.commit_group;")
#define CPWAIT_1() asm volatile("cp.async.wait_group 1;")
#define LDSM4(r, addr) asm volatile( \
    "ldmatrix.sync.aligned.m8n8.x4.shared.b16 {%0,%1,%2,%3}, [%4];" \
    : "=r"((r)[0]), "=r"((r)[1]), "=r"((r)[2]), "=r"((r)[3]) : "r"(addr))
#define HMMA16816(d, a, b0, b1) asm volatile( \
    "mma.sync.aligned.m16n8k16.row.col.f32.f16.f16.f32 " \
    "{%0,%1,%2,%3},{%4,%5,%6,%7},{%8,%9},{%0,%1,%2,%3};" \
    : "+f"((d)[0]), "+f"((d)[1]), "+f"((d)[2]), "+f"((d)[3]) \
    : "r"((a)[0]), "r"((a)[1]), "r"((a)[2]), "r"((a)[3]), "r"(b0), "r"(b1))

__device__ __forceinline__ unsigned short f16bits(float x) {
    return __half_as_ushort(__float2half(x));
}
__device__ __forceinline__ unsigned long long pk2(float x, float y) {
    unsigned long long r;
    asm("mov.b64 %0, {%1, %2};" : "=l"(r) : "f"(x), "f"(y));
    return r;
}
__device__ __forceinline__ void ffma2(unsigned long long& d, unsigned long long a, unsigned long long b) {
    asm("fma.rn.f32x2 %0, %1, %2, %0;" : "+l"(d) : "l"(a), "l"(b));
}
__device__ __forceinline__ float2 unpk(unsigned long long v) {
    float2 f;
    asm("mov.b64 {%0, %1}, %2;" : "=f"(f.x), "=f"(f.y) : "l"(v));
    return f;
}

// ---------------- abs-mean scale ----------------
__global__ __launch_bounds__(256, 2) void absmean_part(const float4* __restrict__ src, long n4, int slot) {
    __shared__ double sred[256];
    double a[8];
#pragma unroll
    for (int c = 0; c < 8; c++) a[c] = 0.0;
    const long stride = (long)gridDim.x * 256;
    long i = (long)blockIdx.x * 256 + threadIdx.x;
    for (; i + 7 * stride < n4; i += 8 * stride) {
        float4 v[8];
#pragma unroll
        for (int c = 0; c < 8; c++) v[c] = src[i + c * stride];
#pragma unroll
        for (int c = 0; c < 8; c++)
            a[c] += (double)(fabsf(v[c].x) + fabsf(v[c].y)) + (double)(fabsf(v[c].z) + fabsf(v[c].w));
    }
    for (; i < n4; i += stride) {
        float4 v = src[i];
        a[0] += (double)(fabsf(v.x) + fabsf(v.y)) + (double)(fabsf(v.z) + fabsf(v.w));
    }
    sred[threadIdx.x] = ((a[0] + a[1]) + (a[2] + a[3])) + ((a[4] + a[5]) + (a[6] + a[7]));
    __syncthreads();
#pragma unroll
    for (int o = 128; o > 0; o >>= 1) {
        if ((int)threadIdx.x < o) sred[threadIdx.x] += sred[threadIdx.x + o];
        __syncthreads();
    }
    if (threadIdx.x == 0) g_part[slot * 512 + blockIdx.x] = sred[0];
}

__global__ void absmean_final(int base) {
    __shared__ double sred[256];
    int slot = base + blockIdx.x, t = threadIdx.x;
    sred[t] = g_part[slot * 512 + t] + g_part[slot * 512 + 256 + t];
    __syncthreads();
#pragma unroll
    for (int o = 128; o > 0; o >>= 1) {
        if (t < o) sred[t] += sred[t + o];
        __syncthreads();
    }
    if (t == 0) {
        double cnt = (slot < 2) ? (double)VV * DD : (double)NNH * DD;
        double s = sred[0] / cnt + 1e-8;
        g_scale[slot]    = (float)s;
        g_scaleinv[slot] = (float)(1.0 / s);
    }
}

// ---------------- weight conversion ----------------
__global__ void tern_quant16(const float4* __restrict__ w, ushort4* __restrict__ q,
                             int slot, int n4) {
    int i = blockIdx.x * 256 + threadIdx.x;
    if (i >= n4) return;
    float inv = g_scaleinv[slot];
    float4 v = w[i];
    ushort4 o;
    o.x = f16bits(rintf(fminf(fmaxf(v.x * inv, -1.f), 1.f)));
    o.y = f16bits(rintf(fminf(fmaxf(v.y * inv, -1.f), 1.f)));
    o.z = f16bits(rintf(fminf(fmaxf(v.z * inv, -1.f), 1.f)));
    o.w = f16bits(rintf(fminf(fmaxf(v.w * inv, -1.f), 1.f)));
    q[i] = o;
}

// ---------------- embedding (fp16 out) + fused wih fp16 conversion ----------------
__global__ void embed_kernel(const int* __restrict__ ids, const float* __restrict__ emb,
                             const float* __restrict__ pos, __half* __restrict__ e16,
                             const float* __restrict__ wih, __half* __restrict__ w16) {
    int i = blockIdx.x * 256 + threadIdx.x;
    int d = i & (DD - 1);
    int s = (i >> 10) & (SS - 1);
    int b = i >> 19;
    int tok = ids[b * SS + s];
    float w = emb[(size_t)tok * DD + d];
    float tn = g_scale[0] * rintf(fminf(fmaxf(w * g_scaleinv[0], -1.f), 1.f));
    e16[i] = __float2half(tn + pos[s * DD + d]);
    w16[i]            = __float2half(wih[i]);
    w16[i + MMDD]     = __float2half(wih[i + MMDD]);
    w16[i + 2 * MMDD] = __float2half(wih[i + 2 * MMDD]);
}

// ---------------- single-pass FP16 GEMM NT, 3-stage cp.async (R11 config) ----------------
#define HG_STAGE 20480
#define HG_SMEM (3 * HG_STAGE)         // 61440 B

template<bool RELU, bool OUT_F16, bool SCALED>
__global__ __launch_bounds__(256) void hgemm(
    const __half* __restrict__ A, const __half* __restrict__ B,
    float* __restrict__ C, __half* __restrict__ C16,
    const float* __restrict__ bias,
    int M, int N, int Kld, int kLen, int slot)
{
    extern __shared__ __align__(16) __half smh[];
    const int t = threadIdx.x;
    const int lane = t & 31;
    const int w = t >> 5;
    const int warpM = (w >> 1) << 5;
    const int warpN = (w & 1) << 6;
    const int bm = blockIdx.y << 7, bn = blockIdx.x << 7;
    const int kOff = blockIdx.z * kLen;
    if (gridDim.z > 1) C += (size_t)blockIdx.z * ((size_t)M * N);

    const __half* gA = A + (size_t)bm * Kld + kOff;
    const __half* gB = B + (size_t)bn * Kld + kOff;
    const unsigned uS = (unsigned)__cvta_generic_to_shared(smh);

    const int lrow = t >> 2;
    const int lcol = (t & 3) << 3;
    const unsigned wro = (unsigned)(lrow * 80 + lcol * 2);

    float acc[2][8][4];
#pragma unroll
    for (int i = 0; i < 2; i++)
#pragma unroll
        for (int j = 0; j < 8; j++)
#pragma unroll
            for (int p = 0; p < 4; p++) acc[i][j][p] = 0.f;

    const int NS = kLen >> 5;

#define HG_LOAD(s) do { \
    unsigned _b = uS + (unsigned)((s) % 3) * HG_STAGE; \
    int _k = (s) << 5; \
    CP16(_b + wro,                     gA + (size_t)lrow * Kld + _k + lcol); \
    CP16(_b + wro + 64 * 80,           gA + (size_t)(lrow + 64) * Kld + _k + lcol); \
    CP16(_b + 10240 + wro,             gB + (size_t)lrow * Kld + _k + lcol); \
    CP16(_b + 10240 + wro + 64 * 80,   gB + (size_t)(lrow + 64) * Kld + _k + lcol); \
    CPCOMMIT(); \
} while (0)

    HG_LOAD(0);
    if (NS > 1) HG_LOAD(1); else CPCOMMIT();

    for (int s = 0; s < NS; s++) {
        CPWAIT_1();
        __syncthreads();
        unsigned base = uS + (unsigned)(s % 3) * HG_STAGE;
#pragma unroll
        for (int kk = 0; kk < 32; kk += 16) {
            uint32_t af[2][4], bf[4][4];
#pragma unroll
            for (int mt = 0; mt < 2; mt++) {
                unsigned ra = base + (unsigned)((warpM + (mt << 4) + (lane & 15)) * 80 + ((kk + ((lane >> 4) << 3)) << 1));
                LDSM4(af[mt], ra);
            }
#pragma unroll
            for (int bj = 0; bj < 4; bj++) {
                unsigned rb = base + 10240u + (unsigned)((warpN + (bj << 4) + ((lane >> 4) << 3) + (lane & 7)) * 80 + ((kk + (((lane >> 3) & 1) << 3)) << 1));
                LDSM4(bf[bj], rb);
            }
#pragma unroll
            for (int mt = 0; mt < 2; mt++)
#pragma unroll
                for (int nt = 0; nt < 8; nt++) {
                    uint32_t b0 = bf[nt >> 1][(nt & 1) << 1];
                    uint32_t b1 = bf[nt >> 1][((nt & 1) << 1) + 1];
                    HMMA16816(acc[mt][nt], af[mt], b0, b1);
                }
        }
        if (s + 2 < NS) HG_LOAD(s + 2); else CPCOMMIT();
    }
#undef HG_LOAD

    const float sc = SCALED ? g_scale[slot] : 1.f;
#pragma unroll
    for (int mt = 0; mt < 2; mt++)
#pragma unroll
        for (int nt = 0; nt < 8; nt++) {
            int row = bm + warpM + (mt << 4) + (lane >> 2);
            int col = bn + warpN + (nt << 3) + ((lane & 3) << 1);
#pragma unroll
            for (int half = 0; half < 2; half++) {
                int r = row + half * 8;
                float v0 = acc[mt][nt][half * 2 + 0];
                float v1 = acc[mt][nt][half * 2 + 1];
                if (SCALED) { v0 *= sc; v1 *= sc; }
                if (bias) { v0 += bias[col]; v1 += bias[col + 1]; }
                if (RELU) { v0 = fmaxf(v0, 0.f); v1 = fmaxf(v1, 0.f); }
                if (OUT_F16) {
                    C16[(size_t)r * N + col]     = __float2half(v0);
                    C16[(size_t)r * N + col + 1] = __float2half(v1);
                } else {
                    C[(size_t)r * N + col]     = v0;
                    C[(size_t)r * N + col + 1] = v1;
                }
            }
        }
}

// ---------------- fused split-K(2) reduce + residual + LayerNorm (+fp16 out) ----------------
__global__ void ln_red(const float* __restrict__ bias, float* __restrict__ x,
                       __half* __restrict__ o16,
                       const float* __restrict__ gamma, const float* __restrict__ beta)
{
    __shared__ float sred[256];
    const int row = blockIdx.x, t = threadIdx.x;
    const size_t off = (size_t)row * DD;
    float4 p0 = ((const float4*)(g_psum + off))[t];
    float4 p1 = ((const float4*)(g_psum + MMDD + off))[t];
    float4 bb = ((const float4*)bias)[t];
    float4 rr = ((const float4*)(x + off))[t];
    float4 v;
    v.x = (p0.x + p1.x) + bb.x + rr.x;
    v.y = (p0.y + p1.y) + bb.y + rr.y;
    v.z = (p0.z + p1.z) + bb.z + rr.z;
    v.w = (p0.w + p1.w) + bb.w + rr.w;

    sred[t] = v.x + v.y + v.z + v.w;
    __syncthreads();
#pragma unroll
    for (int o = 128; o > 0; o >>= 1) { if (t < o) sred[t] += sred[t + o]; __syncthreads(); }
    float mean = sred[0] * (1.f / 1024.f);
    __syncthreads();
    float dx = v.x - mean, dy = v.y - mean, dz = v.z - mean, dw = v.w - mean;
    sred[t] = dx * dx + dy * dy + dz * dz + dw * dw;
    __syncthreads();
#pragma unroll
    for (int o = 128; o > 0; o >>= 1) { if (t < o) sred[t] += sred[t + o]; __syncthreads(); }
    float rstd = rsqrtf(sred[0] * (1.f / 1024.f) + EPSLN);
    float4 g = ((const float4*)gamma)[t];
    float4 b = ((const float4*)beta)[t];
    float4 o4;
    o4.x = dx * rstd * g.x + b.x;
    o4.y = dy * rstd * g.y + b.y;
    o4.z = dz * rstd * g.z + b.z;
    o4.w = dw * rstd * g.w + b.w;
    ((float4*)(x + off))[t] = o4;
    ushort4 h;
    h.x = f16bits(o4.x); h.y = f16bits(o4.y); h.z = f16bits(o4.z); h.w = f16bits(o4.w);
    ((ushort4*)(o16 + off))[t] = h;
}

// ---------------- final LayerNorm (fp16 out) ----------------
__global__ void ln_final(const float* __restrict__ in, __half* __restrict__ o16,
                         const float* __restrict__ gamma, const float* __restrict__ beta)
{
    __shared__ float sred[256];
    const int row = blockIdx.x, t = threadIdx.x;
    const float4 v = ((const float4*)(in + (size_t)row * DD))[t];
    sred[t] = v.x + v.y + v.z + v.w;
    __syncthreads();
#pragma unroll
    for (int o = 128; o > 0; o >>= 1) { if (t < o) sred[t] += sred[t + o]; __syncthreads(); }
    float mean = sred[0] * (1.f / 1024.f);
    __syncthreads();
    float dx = v.x - mean, dy = v.y - mean, dz = v.z - mean, dw = v.w - mean;
    sred[t] = dx * dx + dy * dy + dz * dz + dw * dw;
    __syncthreads();
#pragma unroll
    for (int o = 128; o > 0; o >>= 1) { if (t < o) sred[t] += sred[t + o]; __syncthreads(); }
    float rstd = rsqrtf(sred[0] * (1.f / 1024.f) + EPSLN);
    float4 g = ((const float4*)gamma)[t];
    float4 b = ((const float4*)beta)[t];
    ushort4 h;
    h.x = f16bits(dx * rstd * g.x + b.x);
    h.y = f16bits(dy * rstd * g.y + b.y);
    h.z = f16bits(dz * rstd * g.z + b.z);
    h.w = f16bits(dw * rstd * g.w + b.w);
    ((ushort4*)(o16 + (size_t)row * DD))[t] = h;
}

// ---------------- flag-array grid barrier ----------------
__device__ __forceinline__ void gbarf(unsigned k) {
    __syncthreads();
    if (threadIdx.x == 0) {
        __threadfence();
        g_flags[(unsigned)blockIdx.x * 32] = k;
    }
    if (threadIdx.x < GRU_CTAS) {
        while (g_flags[(unsigned)threadIdx.x * 32] < k) { }
    }
    __syncthreads();
}

// ---------------- persistent GRU ----------------
__global__ __launch_bounds__(192, 1) void gru_kernel(
    const float* __restrict__ gi, const float* __restrict__ whh,
    const float* __restrict__ bhh, float* __restrict__ x,
    __half* __restrict__ x16)
{
    __shared__ float hs[2048];
    __shared__ float sgh[48];
    __shared__ float sbh[24];
    const int tid = threadIdx.x;
    const int base = blockIdx.x * 8;
    const int r = tid >> 3, j = tid & 7;
    const int gg = r >> 3, ddim = r & 7;

    float4 wreg[32];
    const float* wrow = whh + (size_t)(gg * 1024 + base + ddim) * 1024;
#pragma unroll
    for (int i = 0; i < 32; i++)
        wreg[i] = *(const float4*)(wrow + (i * 8 + j) * 4);

    if (tid < 24) sbh[tid] = bhh[(tid >> 3) * 1024 + base + (tid & 7)];
    if (tid < 16) {
        int b = tid & 1, d0 = base + (tid >> 1);
        g_h[0][2 * d0 + b] = 0.f;
    }
    gbarf(1);

    for (int s = 0; s < SS; s++) {
        const int rb = s & 1, wb = rb ^ 1;

        float ir = 0.f, iz = 0.f, inn = 0.f;
        if (tid < 16) {
            int b = tid & 1, d0 = tid >> 1;
            int dg = base + d0;
            const float* gim = gi + ((size_t)b * SS + s) * 3072;
            ir  = __ldcg(gim + dg);
            iz  = __ldcg(gim + 1024 + dg);
            inn = __ldcg(gim + 2048 + dg);
        }

        for (int idx = tid; idx < 512; idx += 192)
            ((float4*)hs)[idx] = __ldcg((const float4*)&g_h[rb][0] + idx);
        __syncthreads();

        unsigned long long ac0 = 0ull, ac1 = 0ull, ac2 = 0ull, ac3 = 0ull;
#pragma unroll
        for (int i = 0; i < 32; i++) {
            int c4 = i * 8 + j;
            float4 hA = ((const float4*)hs)[c4 * 2];
            float4 hB = ((const float4*)hs)[c4 * 2 + 1];
            float4 w = wreg[i];
            ffma2(ac0, pk2(w.x, w.x), pk2(hA.x, hA.y));
            ffma2(ac1, pk2(w.y, w.y), pk2(hA.z, hA.w));
            ffma2(ac2, pk2(w.z, w.z), pk2(hB.x, hB.y));
            ffma2(ac3, pk2(w.w, w.w), pk2(hB.z, hB.w));
        }
        float2 s0 = unpk(ac0), s1 = unpk(ac1), s2 = unpk(ac2), s3 = unpk(ac3);
        float acc0 = (s0.x + s1.x) + (s2.x + s3.x);
        float acc1 = (s0.y + s1.y) + (s2.y + s3.y);
#pragma unroll
        for (int o = 4; o; o >>= 1) {
            acc0 += __shfl_down_sync(0xffffffffu, acc0, o);
            acc1 += __shfl_down_sync(0xffffffffu, acc1, o);
        }
        if (j == 0) { sgh[r * 2] = acc0 + sbh[r]; sgh[r * 2 + 1] = acc1 + sbh[r]; }
        __syncthreads();

        if (tid < 16) {
            int b = tid & 1, d0 = tid >> 1;
            int dg = base + d0;
            float hr = sgh[d0 * 2 + b], hz = sgh[(8 + d0) * 2 + b], hn = sgh[(16 + d0) * 2 + b];
            float rg = 1.f / (1.f + expf(-(ir + hr)));
            float zg = 1.f / (1.f + expf(-(iz + hz)));
            float ng = tanhf(inn + rg * hn);
            float hp = hs[2 * dg + b];
            float hv = (1.f - zg) * ng + zg * hp;
            __stcg(&g_h[wb][2 * dg + b], hv);
            size_t m = (size_t)b * SS + s;
            x[m * 1024 + dg] = hv;
            x16[m * 1024 + dg] = __float2half(hv);
        }
        if (s + 1 < SS) gbarf(2 + s);
    }

    if (tid == 0) {
        __threadfence();
        unsigned a = atomicAdd(&g_ack, 1u);
        if (a == GRU_CTAS - 1) {
            for (int i = 0; i < GRU_CTAS; i++) g_flags[i * 32] = 0;
            __threadfence();
            g_ack = 0;
            __threadfence();
        }
    }
}

// ---------------- launch ----------------
extern "C" void kernel_launch(void* const* d_in, const int* in_sizes, int n_in,
                              void* d_out, int out_size) {
    const int*   ids     = (const int*)  d_in[0];
    const float* emb     = (const float*)d_in[1];
    const float* pos     = (const float*)d_in[2];
    const float* gru_wih = (const float*)d_in[3];
    const float* gru_whh = (const float*)d_in[4];
    const float* gru_bih = (const float*)d_in[5];
    const float* gru_bhh = (const float*)d_in[6];
    const float* syn_w   = (const float*)d_in[7];
    const float* syn_b   = (const float*)d_in[8];
    const float* out_w   = (const float*)d_in[9];
    const float* out_b   = (const float*)d_in[10];
    const float* ln_g    = (const float*)d_in[11];
    const float* ln_b    = (const float*)d_in[12];
    const float* on_g    = (const float*)d_in[13];
    const float* on_b    = (const float*)d_in[14];
    const float* head_w  = (const float*)d_in[15];
    const float* head_b  = (const float*)d_in[16];
    float* logits = (float*)d_out;

    float *xg, *gig, *psg;
    __half *w16ih, *q16syn, *q16out, *q16head, *x16, *h16, *y16;
    cudaGetSymbolAddress((void**)&xg,   g_x);
    cudaGetSymbolAddress((void**)&gig,  g_gi);
    cudaGetSymbolAddress((void**)&psg,  g_psum);
    cudaGetSymbolAddress((void**)&w16ih,  g_w16ih);
    cudaGetSymbolAddress((void**)&q16syn,  g_q16syn);
    cudaGetSymbolAddress((void**)&q16out,  g_q16out);
    cudaGetSymbolAddress((void**)&q16head, g_q16head);
    cudaGetSymbolAddress((void**)&x16, g_x16);
    cudaGetSymbolAddress((void**)&h16, g_h16);
    cudaGetSymbolAddress((void**)&y16, g_y16);

    static cudaStream_t s1, s2;
    static cudaEvent_t evRoot, ev1, ev2;
    static bool init_done = false;
    if (!init_done) {
        cudaFuncSetAttribute(hgemm<true,  true,  true >, cudaFuncAttributeMaxDynamicSharedMemorySize, HG_SMEM);
        cudaFuncSetAttribute(hgemm<false, false, true >, cudaFuncAttributeMaxDynamicSharedMemorySize, HG_SMEM);
        cudaFuncSetAttribute(hgemm<false, false, false>, cudaFuncAttributeMaxDynamicSharedMemorySize, HG_SMEM);
        cudaStreamCreateWithFlags(&s1, cudaStreamNonBlocking);
        cudaStreamCreateWithFlags(&s2, cudaStreamNonBlocking);
        cudaEventCreateWithFlags(&evRoot, cudaEventDisableTiming);
        cudaEventCreateWithFlags(&ev1, cudaEventDisableTiming);
        cudaEventCreateWithFlags(&ev2, cudaEventDisableTiming);
        init_done = true;
    }

    long nVD4 = (long)VV * DD / 4, nND4 = (long)NNH * DD / 4;

    // fork side streams FIRST so prep overlaps the main chain (R11 topology)
    cudaEventRecord(evRoot, 0);
    cudaStreamWaitEvent(s1, evRoot, 0);
    cudaStreamWaitEvent(s2, evRoot, 0);

    // main stream: emb scale -> embed(+wih cvt) -> in-proj -> GRU
    absmean_part<<<512, 256>>>((const float4*)emb, nVD4, 0);
    absmean_final<<<1, 256>>>(0);
    embed_kernel<<<4096, 256>>>(ids, emb, pos, y16, gru_wih, w16ih);
    hgemm<false, false, false><<<dim3(3072 / 128, MROWS / 128, 1), 256, HG_SMEM>>>(
        y16, w16ih, gig, (__half*)0, gru_bih, MROWS, 3072, DD, DD, 0);
    gru_kernel<<<GRU_CTAS, 192>>>(gig, gru_whh, gru_bhh, xg, x16);

    // side stream 1: layer weight scales + fp16 quantization
    for (int l = 0; l < 4; l++) {
        absmean_part<<<512, 256, 0, s1>>>((const float4*)(syn_w + (size_t)l * NNH * DD), nND4, 2 + l);
        absmean_part<<<512, 256, 0, s1>>>((const float4*)(out_w + (size_t)l * DD * NNH), nND4, 6 + l);
    }
    absmean_final<<<8, 256, 0, s1>>>(2);
    for (int l = 0; l < 4; l++) {
        tern_quant16<<<(int)(nND4 / 256), 256, 0, s1>>>((const float4*)(syn_w + (size_t)l * NNH * DD),
                                                        (ushort4*)(q16syn + (size_t)l * NNH * DD), 2 + l, (int)nND4);
        tern_quant16<<<(int)(nND4 / 256), 256, 0, s1>>>((const float4*)(out_w + (size_t)l * DD * NNH),
                                                        (ushort4*)(q16out + (size_t)l * DD * NNH), 6 + l, (int)nND4);
    }
    cudaEventRecord(ev1, s1);

    // side stream 2: head scale + fp16 quantization
    absmean_part<<<512, 256, 0, s2>>>((const float4*)head_w, nVD4, 1);
    absmean_final<<<1, 256, 0, s2>>>(1);
    tern_quant16<<<(int)(nVD4 / 256), 256, 0, s2>>>((const float4*)head_w, (ushort4*)q16head, 1, (int)nVD4);
    cudaEventRecord(ev2, s2);

    // join layer-weight stream, MLP (single-pass fp16, split-K=2)
    cudaStreamWaitEvent(0, ev1, 0);
    for (int l = 0; l < 4; l++) {
        hgemm<true, true, true><<<dim3(NNH / 128, MROWS / 128, 1), 256, HG_SMEM>>>(
            x16, q16syn + (size_t)l * NNH * DD, (float*)0, h16,
            syn_b + (size_t)l * NNH, MROWS, NNH, DD, DD, 2 + l);
        hgemm<false, false, true><<<dim3(DD / 128, MROWS / 128, 2), 256, HG_SMEM>>>(
            h16, q16out + (size_t)l * DD * NNH, psg, (__half*)0,
            (const float*)0, MROWS, DD, NNH, NNH / 2, 6 + l);
        ln_red<<<MROWS, 256>>>(out_b + (size_t)l * DD, xg, x16,
                               ln_g + (size_t)l * DD, ln_b + (size_t)l * DD);
    }

    // join head stream, final LN + head
    cudaStreamWaitEvent(0, ev2, 0);
    ln_final<<<MROWS, 256>>>(xg, y16, on_g, on_b);
    hgemm<false, false, true><<<dim3(VV / 128, MROWS / 128, 1), 256, HG_SMEM>>>(
        y16, q16head, logits, (__half*)0, head_b, MROWS, VV, DD, DD, 1);
}